// round 11
// baseline (speedup 1.0000x reference)
#include <cuda_runtime.h>
#include <cstdint>
#include <math.h>

#define CB 4
#define CS 1024
#define CH 1024
#define CNH 16
#define CDH 64
#define CM (CB*CS)
#define CLIPV 2.5f

// ---------------- scratch (device globals; no allocations allowed) ----------
__device__ unsigned g_max[8];   // 0 hidden,1 Wq,2 Wk,3 Wv,4 q,5 k,6 v,7 probs
__device__ float  g_xd[(size_t)CM*CH];                // dequant hidden (bit-exact)
__device__ float  g_wd[3][(size_t)CH*CH];             // dequant weights (bit-exact)
__device__ float  g_lin[3][(size_t)CM*CH];            // q,k,v fp32 [B,S,H]
__device__ float  g_qf[(size_t)CB*CNH*CS*CDH];        // dequant q [b,h,s,d] fp32
__device__ float  g_kf[(size_t)CB*CNH*CS*CDH];        // dequant k [b,h,s,d] fp32
__device__ int8_t g_v8t[(size_t)CB*CNH*CDH*CS];       // v codes [b,h,d,s]
__device__ float  g_sc_fb[(size_t)CB*CNH*CS*CS];      // fallback scores
__device__ float  g_pr_fb[(size_t)CB*CNH*CS*CS];      // fallback probs

__device__ __forceinline__ float clipf(float v){ return fminf(fmaxf(v,-CLIPV),CLIPV); }
__device__ __forceinline__ float slot_m(int s){ return fmaxf(__uint_as_float(g_max[s]),1e-8f); }

// Eigen pexp<float> replica, exact op-for-op (Estrin split y/y1/y2).
// Domain here: x in [-46, 0]; clamps never fire; ldexp scale exact.
__device__ __forceinline__ float exp_eig(float x){
  float m = floorf(__fmaf_rn(x, 1.44269504088896341f, 0.5f));
  float r = __fmaf_rn(m, -0.693359375f, x);
  r = __fmaf_rn(m, 2.12194440e-4f, r);
  float r2 = __fmul_rn(r, r);
  float r3 = __fmul_rn(r2, r);
  float y, y1, y2;
  y  = __fmaf_rn(1.9875691500e-4f, r, 1.3981999507e-3f);
  y1 = __fmaf_rn(4.1665795894e-2f, r, 1.6666665459e-1f);
  y2 = __fadd_rn(r, 1.0f);
  y  = __fmaf_rn(y, r, 8.3334519073e-3f);
  y1 = __fmaf_rn(y1, r, 5.0000001201e-1f);
  y  = __fmaf_rn(y, r3, y1);
  y  = __fmaf_rn(y, r2, y2);
  int mi = (int)m;                       // in [-67, 1]: single scale exact
  return __fmul_rn(y, __int_as_float((mi + 127) << 23));
}

__global__ void k_init(){ if(threadIdx.x<8) g_max[threadIdx.x]=0u; }

__global__ void k_absmax(const float* __restrict__ x, int n4, int slot){
  float m=0.f;
  for (int i=blockIdx.x*blockDim.x+threadIdx.x; i<n4; i+=gridDim.x*blockDim.x){
    float4 v=((const float4*)x)[i];
    m=fmaxf(m,fabsf(clipf(v.x))); m=fmaxf(m,fabsf(clipf(v.y)));
    m=fmaxf(m,fabsf(clipf(v.z))); m=fmaxf(m,fabsf(clipf(v.w)));
  }
  #pragma unroll
  for(int o=16;o;o>>=1) m=fmaxf(m,__shfl_xor_sync(0xffffffffu,m,o));
  if((threadIdx.x&31)==0) atomicMax(&g_max[slot],__float_as_uint(m));
}

// dequant d = fl(round(clip(x)*s)/s), s = fl(127/m): bit-exact sym_quant fwd
__global__ void k_quant(const float* __restrict__ x, int n, int slot, int wid){
  float* o = (wid<0)? g_xd : g_wd[wid];
  float s = __fdiv_rn(127.f, slot_m(slot));
  for(int i=blockIdx.x*blockDim.x+threadIdx.x;i<n;i+=gridDim.x*blockDim.x){
    float q = rintf(__fmul_rn(clipf(x[i]), s));
    o[i] = __fdiv_rn(q, s);
  }
}

// ---- fp32 projection GEMM, Eigen-gebp balanced panels [512,512] -----------
// (Grace l1d=64KB via sysconf -> max_kc=1016 > K -> balanced kc = 512.)
// Per output: ascending-k fp32 FMA chain within panel from 0; panels combined
// by one fp32 add; bias added last. Boundary at k=512.
__global__ __launch_bounds__(256) void k_gemm(const float* __restrict__ bq,
                                              const float* __restrict__ bk,
                                              const float* __restrict__ bv){
  __shared__ float As[8][68];
  __shared__ float Bs[8][68];
  int which = blockIdx.z;
  const float* bias = (which==0)? bq : (which==1)? bk : bv;
  const float* A = g_xd;
  const float* W = g_wd[which];
  float* C = g_lin[which];
  int bm=blockIdx.x, bn=blockIdx.y;
  int tid=threadIdx.x, ty=tid>>4, tx=tid&15;
  const float* Ab = A + (size_t)bm*64*CH;
  const float* Wb = W + (size_t)bn*64*CH;
  int row=tid>>2, kp=(tid&3)*2;
  float acc[4][4]={}, tot[4][4]={};
  for(int kt=0;kt<128;kt++){
    if(kt==64){                          // panel boundary k=512
      #pragma unroll
      for(int i=0;i<4;i++)
        #pragma unroll
        for(int j=0;j<4;j++){ tot[i][j]=__fadd_rn(tot[i][j],acc[i][j]); acc[i][j]=0.f; }
    }
    float2 va=*(const float2*)(Ab+(size_t)row*CH+kt*8+kp);
    float2 vb=*(const float2*)(Wb+(size_t)row*CH+kt*8+kp);
    __syncthreads();
    As[kp][row]=va.x; As[kp+1][row]=va.y;
    Bs[kp][row]=vb.x; Bs[kp+1][row]=vb.y;
    __syncthreads();
    #pragma unroll
    for(int kk=0;kk<8;kk++){
      float a[4],b[4];
      #pragma unroll
      for(int i=0;i<4;i++) a[i]=As[kk][ty*4+i];
      #pragma unroll
      for(int j=0;j<4;j++) b[j]=Bs[kk][tx*4+j];
      #pragma unroll
      for(int i=0;i<4;i++)
        #pragma unroll
        for(int j=0;j<4;j++) acc[i][j]=__fmaf_rn(a[i],b[j],acc[i][j]);
    }
  }
  float lm=0.f;
  #pragma unroll
  for(int i=0;i<4;i++){
    int m=bm*64+ty*4+i;
    #pragma unroll
    for(int j=0;j<4;j++){
      int n=bn*64+tx*4+j;
      float c=__fadd_rn(__fadd_rn(tot[i][j],acc[i][j]), bias[n]);
      C[(size_t)m*CH+n]=c;
      lm=fmaxf(lm,fabsf(clipf(c)));
    }
  }
  #pragma unroll
  for(int o=16;o;o>>=1) lm=fmaxf(lm,__shfl_xor_sync(0xffffffffu,lm,o));
  if((tid&31)==0) atomicMax(&g_max[4+which],__float_as_uint(lm));
}

// ---- dequantized q/k (fp32, head-major): bit-exact sym_quant(q/k) ---------
__global__ void k_quant_headsf(int which){
  const float* src = g_lin[which];
  float* dst = (which==0)? g_qf : g_kf;
  float s = __fdiv_rn(127.f, slot_m(4+which));
  const int n = CB*CNH*CS*CDH;
  for(int i=blockIdx.x*blockDim.x+threadIdx.x;i<n;i+=gridDim.x*blockDim.x){
    int d=i&63, s_=(i>>6)&1023, h=(i>>16)&15, b=i>>20;
    float v=src[((size_t)(b*CS+s_))*CH + h*CDH + d];
    float q=rintf(__fmul_rn(clipf(v),s));
    dst[i]=__fdiv_rn(q, s);
  }
}

// ---- v: write v_q output (bit-exact) + transposed int8 codes ---------------
__global__ void k_quant_v(float* __restrict__ vq_out){
  const float* src=g_lin[2];
  float s = __fdiv_rn(127.f, slot_m(6));
  const int n = CB*CNH*CS*CDH;
  for(int i=blockIdx.x*blockDim.x+threadIdx.x;i<n;i+=gridDim.x*blockDim.x){
    int d=i&63, s_=(i>>6)&1023, h=(i>>16)&15, b=i>>20;
    float v=src[((size_t)(b*CS+s_))*CH + h*CDH + d];
    float vc=clipf(v);
    float q=rintf(__fmul_rn(vc,s));
    if(vq_out) vq_out[i]=__fdiv_rn(q, s);
    g_v8t[(((size_t)(b*CNH+h))*CDH+d)*CS + s_]=(int8_t)(int)q;
  }
}

// ---- scores: bit-exact ascending-d fp32 FMA chain, *0.125 (exact), +mask ---
__global__ __launch_bounds__(256) void k_scores(const float* __restrict__ mask,
                                                float* __restrict__ ss){
  extern __shared__ float sm[];
  float* qs = sm;             // [64 d][132]
  float* ks = sm + 64*132;    // [64 d][132]
  int rt=blockIdx.x, ct=blockIdx.y, bh=blockIdx.z;
  int b = bh>>4;
  int tid=threadIdx.x, ty=tid>>4, tx=tid&15;
  const float* qg = g_qf + ((size_t)bh*CS + (size_t)rt*128)*CDH;
  const float* kg = g_kf + ((size_t)bh*CS + (size_t)ct*128)*CDH;
  for(int idx=tid; idx<128*16; idx+=256){
    int d4=idx&15, row=idx>>4;
    float4 v = *(const float4*)(qg + (size_t)row*CDH + d4*4);
    qs[(d4*4+0)*132+row]=v.x; qs[(d4*4+1)*132+row]=v.y;
    qs[(d4*4+2)*132+row]=v.z; qs[(d4*4+3)*132+row]=v.w;
    float4 u = *(const float4*)(kg + (size_t)row*CDH + d4*4);
    ks[(d4*4+0)*132+row]=u.x; ks[(d4*4+1)*132+row]=u.y;
    ks[(d4*4+2)*132+row]=u.z; ks[(d4*4+3)*132+row]=u.w;
  }
  __syncthreads();
  float acc[8][8]={};
  for(int d=0; d<64; d++){               // ascending-d chain: matches ref
    float av[8], bv[8];
    #pragma unroll
    for(int i=0;i<8;i++) av[i]=qs[d*132 + ty*8 + i];
    #pragma unroll
    for(int j=0;j<8;j++) bv[j]=ks[d*132 + tx + 16*j];
    #pragma unroll
    for(int i=0;i<8;i++)
      #pragma unroll
      for(int j=0;j<8;j++) acc[i][j]=__fmaf_rn(av[i],bv[j],acc[i][j]);
  }
  #pragma unroll
  for(int i=0;i<8;i++){
    int row = rt*128 + ty*8 + i;
    #pragma unroll
    for(int j=0;j<8;j++){
      int col = ct*128 + tx + 16*j;
      float sv = __fadd_rn(__fmul_rn(acc[i][j], 0.125f), mask[b*CS+col]);
      ss[((size_t)bh*CS + row)*CS + col] = sv;
    }
  }
}

// ---- softmax per row: max, Eigen-exp, sum, divide; fused pmax --------------
__global__ __launch_bounds__(256) void k_softmax(const float* __restrict__ ssrc,
                                                 float* __restrict__ pdst){
  __shared__ float red[256];
  size_t base = (size_t)blockIdx.x * CS;
  int tid=threadIdx.x;
  float4 x = *(const float4*)(ssrc + base + tid*4);
  float m = fmaxf(fmaxf(x.x,x.y), fmaxf(x.z,x.w));
  red[tid]=m; __syncthreads();
  #pragma unroll
  for(int o=128;o;o>>=1){ if(tid<o) red[tid]=fmaxf(red[tid],red[tid+o]); __syncthreads(); }
  float rowmax = red[0]; __syncthreads();
  float e0=exp_eig(__fsub_rn(x.x,rowmax));
  float e1=exp_eig(__fsub_rn(x.y,rowmax));
  float e2=exp_eig(__fsub_rn(x.z,rowmax));
  float e3=exp_eig(__fsub_rn(x.w,rowmax));
  red[tid]=((e0+e1)+(e2+e3)); __syncthreads();
  #pragma unroll
  for(int o=128;o;o>>=1){ if(tid<o) red[tid]=red[tid]+red[tid+o]; __syncthreads(); }
  float sum = red[0];
  float4 p;
  p.x=__fdiv_rn(e0,sum); p.y=__fdiv_rn(e1,sum);
  p.z=__fdiv_rn(e2,sum); p.w=__fdiv_rn(e3,sum);
  *(float4*)(pdst + base + tid*4) = p;
  if(tid==0) atomicMax(&g_max[7],__float_as_uint(__fdiv_rn(1.f,sum)));
}

// ---- PV: context_ = probs_q @ v_q (exact int8 dp4a + double dequant) -------
__global__ __launch_bounds__(256) void k_pv(const float* __restrict__ probs_in,
     float* __restrict__ ctxp, float* __restrict__ ctx){
  __shared__ int ps[128][33];
  __shared__ int vs[64][33];
  int mt=blockIdx.x, bh=blockIdx.y;
  int b=bh>>4, h=bh&15;
  const float* pg = probs_in + (((size_t)bh)*CS + (size_t)mt*128)*CS;
  const int* vtg = (const int*)(g_v8t + (size_t)bh*CDH*CS);
  float sp = __fdiv_rn(127.f, slot_m(7));
  int tid=threadIdx.x, ty=tid>>4, tx=tid&15;
  int acc[8][4]={};
  for(int kc=0;kc<8;kc++){
    for(int idx=tid; idx<128*32; idx+=256){
      int r=idx>>5, w=idx&31;
      float4 p4=*(const float4*)(pg + (size_t)r*CS + kc*128 + w*4);
      int b0=((int)rintf(__fmul_rn(p4.x,sp)))&0xFF;
      int b1=((int)rintf(__fmul_rn(p4.y,sp)))&0xFF;
      int b2=((int)rintf(__fmul_rn(p4.z,sp)))&0xFF;
      int b3=((int)rintf(__fmul_rn(p4.w,sp)))&0xFF;
      ps[r][w]= b0|(b1<<8)|(b2<<16)|(b3<<24);
    }
    for(int idx=tid; idx<64*32; idx+=256){
      int d=idx>>5, w=idx&31;
      vs[d][w]=vtg[(size_t)d*(CS/4)+kc*32+w];
    }
    __syncthreads();
    #pragma unroll
    for(int w=0;w<32;w++){
      int a[8],bb[4];
      #pragma unroll
      for(int i=0;i<8;i++) a[i]=ps[ty*8+i][w];
      #pragma unroll
      for(int j=0;j<4;j++) bb[j]=vs[tx*4+j][w];
      #pragma unroll
      for(int i=0;i<8;i++)
        #pragma unroll
        for(int j=0;j<4;j++) acc[i][j]=__dp4a(a[i],bb[j],acc[i][j]);
    }
    __syncthreads();
  }
  double inv = 1.0/((double)__fdiv_rn(127.f,slot_m(7))*(double)__fdiv_rn(127.f,slot_m(6)));
  #pragma unroll
  for(int i=0;i<8;i++){
    int srow=mt*128+ty*8+i;
    #pragma unroll
    for(int j=0;j<4;j++){
      int d=tx*4+j;
      float c=(float)((double)acc[i][j]*inv);
      if(ctxp) ctxp[(((size_t)bh)*CS+srow)*CDH+d]=c;
      ctx[((size_t)(b*CS+srow))*CH + h*CDH + d]=c;
    }
  }
}

// ---------------- launch ----------------
extern "C" void kernel_launch(void* const* d_in, const int* in_sizes, int n_in,
                              void* d_out, int out_size){
  const float* hs  =(const float*)d_in[0];
  const float* mask=(const float*)d_in[1];
  const float* Wq  =(const float*)d_in[2];
  const float* bq  =(const float*)d_in[3];
  const float* Wk  =(const float*)d_in[4];
  const float* bk  =(const float*)d_in[5];
  const float* Wv  =(const float*)d_in[6];
  const float* bv  =(const float*)d_in[7];
  float* out=(float*)d_out;

  const size_t n_ctx=(size_t)CB*CS*CH;
  const size_t n_sc =(size_t)CB*CNH*CS*CS;
  float *ctx=out, *scores=nullptr, *probs=nullptr, *ctxp=nullptr, *vq=nullptr;
  if((size_t)out_size >= 3*n_ctx + 2*n_sc){
    scores=out+n_ctx; probs=scores+n_sc; ctxp=probs+n_sc; vq=ctxp+n_ctx;
  }
  float* sc_buf = scores;
  float* pr_buf = probs;
  if(!sc_buf){ void* p; cudaGetSymbolAddress(&p, g_sc_fb); sc_buf=(float*)p; }
  if(!pr_buf){ void* p; cudaGetSymbolAddress(&p, g_pr_fb); pr_buf=(float*)p; }

  k_init<<<1,32>>>();
  k_absmax<<<512,256>>>(hs, CM*CH/4, 0);
  k_absmax<<<256,256>>>(Wq, CH*CH/4, 1);
  k_absmax<<<256,256>>>(Wk, CH*CH/4, 2);
  k_absmax<<<256,256>>>(Wv, CH*CH/4, 3);

  k_quant<<<2048,256>>>(hs, CM*CH, 0, -1);
  k_quant<<<1024,256>>>(Wq, CH*CH, 1, 0);
  k_quant<<<1024,256>>>(Wk, CH*CH, 2, 1);
  k_quant<<<1024,256>>>(Wv, CH*CH, 3, 2);

  dim3 gg(CM/64, CH/64, 3);
  k_gemm<<<gg,256>>>(bq,bk,bv);

  k_quant_headsf<<<2048,256>>>(0);
  k_quant_headsf<<<2048,256>>>(1);
  k_quant_v<<<2048,256>>>(vq);

  const int sc_smem = 64*132*2*sizeof(float);   // 67,584 B
  cudaFuncSetAttribute(k_scores, cudaFuncAttributeMaxDynamicSharedMemorySize, sc_smem);
  k_scores<<<dim3(CS/128,CS/128,CB*CNH),256,sc_smem>>>(mask, sc_buf);

  k_softmax<<<CB*CNH*CS,256>>>(sc_buf, pr_buf);

  k_pv<<<dim3(CS/128,CB*CNH),256>>>(pr_buf, ctxp, ctx);
}